// round 4
// baseline (speedup 1.0000x reference)
#include <cuda_runtime.h>

// SSIM-style loss (sum over channels+window, /ws^2), single fused kernel.
// x, y: (32, 3, 512, 512) fp32. out: (32,) fp32.
//
// One CTA per (batch, window-row): 1024 CTAs x 384 threads.
// Channel split across thread groups: c = tid>>7, t = tid&127 (float4 col).
// Each thread streams 16 rows x 1 channel (16 LDG.128 per input), fully
// coalesced per warp. regs capped via launch_bounds(384,4) -> 4 CTA/SM,
// 48 warps/SM (75% occ) vs 28 before -> more chip-wide MLP.
// Channel partials combine in smem BEFORE the SSIM nonlinearity.
// Per-batch ticket: last CTA of each batch folds 32 row-partials -> out[b].

#define IMG_H 512
#define IMG_W 512
#define NCH 3
#define WS 16
#define NWIN_X 32
#define NWIN_Y 32
#define NBATCH 32
#define W4 (IMG_W / 4)

static __device__ float        g_partial[NBATCH * NWIN_Y];
static __device__ unsigned int g_ticket[NBATCH];

__global__ __launch_bounds__(384, 4)
void ssim_fused_kernel(const float* __restrict__ x, const float* __restrict__ y,
                       float* __restrict__ out) {
    const int tid = threadIdx.x;
    const int c   = tid >> 7;              // channel 0..2
    const int t   = tid & 127;             // float4 column 0..127
    const int br  = blockIdx.x & 31;       // window row
    const int b   = blockIdx.x >> 5;       // batch

    const size_t img = (size_t)NCH * IMG_H * IMG_W;
    const float4* __restrict__ xp = (const float4*)(x + (size_t)b * img);
    const float4* __restrict__ yp = (const float4*)(y + (size_t)b * img);

    float sx = 0.f, sy = 0.f, sxx = 0.f, syy = 0.f, sxy = 0.f;

    size_t base = (size_t)c * (IMG_H * W4) + (size_t)(br * WS) * W4 + t;
#pragma unroll
    for (int h0 = 0; h0 < WS; h0 += 2) {
        float4 vx0 = __ldcs(xp + base + (size_t)(h0    ) * W4);
        float4 vx1 = __ldcs(xp + base + (size_t)(h0 + 1) * W4);
        float4 vy0 = __ldcs(yp + base + (size_t)(h0    ) * W4);
        float4 vy1 = __ldcs(yp + base + (size_t)(h0 + 1) * W4);

        sx += (vx0.x + vx0.y) + (vx0.z + vx0.w);
        sy += (vy0.x + vy0.y) + (vy0.z + vy0.w);
        sxx = fmaf(vx0.x, vx0.x, sxx); sxx = fmaf(vx0.y, vx0.y, sxx);
        sxx = fmaf(vx0.z, vx0.z, sxx); sxx = fmaf(vx0.w, vx0.w, sxx);
        syy = fmaf(vy0.x, vy0.x, syy); syy = fmaf(vy0.y, vy0.y, syy);
        syy = fmaf(vy0.z, vy0.z, syy); syy = fmaf(vy0.w, vy0.w, syy);
        sxy = fmaf(vx0.x, vy0.x, sxy); sxy = fmaf(vx0.y, vy0.y, sxy);
        sxy = fmaf(vx0.z, vy0.z, sxy); sxy = fmaf(vx0.w, vy0.w, sxy);

        sx += (vx1.x + vx1.y) + (vx1.z + vx1.w);
        sy += (vy1.x + vy1.y) + (vy1.z + vy1.w);
        sxx = fmaf(vx1.x, vx1.x, sxx); sxx = fmaf(vx1.y, vx1.y, sxx);
        sxx = fmaf(vx1.z, vx1.z, sxx); sxx = fmaf(vx1.w, vx1.w, sxx);
        syy = fmaf(vy1.x, vy1.x, syy); syy = fmaf(vy1.y, vy1.y, syy);
        syy = fmaf(vy1.z, vy1.z, syy); syy = fmaf(vy1.w, vy1.w, syy);
        sxy = fmaf(vx1.x, vy1.x, sxy); sxy = fmaf(vx1.y, vy1.y, sxy);
        sxy = fmaf(vx1.z, vy1.z, sxy); sxy = fmaf(vx1.w, vy1.w, sxy);
    }

    // fold 4 adjacent threads (16 cols of one window, one channel)
#pragma unroll
    for (int off = 1; off < 4; off <<= 1) {
        sx  += __shfl_xor_sync(0xffffffffu, sx,  off);
        sy  += __shfl_xor_sync(0xffffffffu, sy,  off);
        sxx += __shfl_xor_sync(0xffffffffu, sxx, off);
        syy += __shfl_xor_sync(0xffffffffu, syy, off);
        sxy += __shfl_xor_sync(0xffffffffu, sxy, off);
    }

    __shared__ float s_sums[NCH][NWIN_X][5];
    __shared__ unsigned int s_ticket;
    if ((t & 3) == 0) {
        const int win = t >> 2;
        s_sums[c][win][0] = sx;
        s_sums[c][win][1] = sy;
        s_sums[c][win][2] = sxx;
        s_sums[c][win][3] = syy;
        s_sums[c][win][4] = sxy;
    }
    __syncthreads();

    if (tid < 32) {
        // combine channels, compute SSIM for window 'tid'
        float S0 = s_sums[0][tid][0] + s_sums[1][tid][0] + s_sums[2][tid][0];
        float S1 = s_sums[0][tid][1] + s_sums[1][tid][1] + s_sums[2][tid][1];
        float S2 = s_sums[0][tid][2] + s_sums[1][tid][2] + s_sums[2][tid][2];
        float S3 = s_sums[0][tid][3] + s_sums[1][tid][3] + s_sums[2][tid][3];
        float S4 = s_sums[0][tid][4] + s_sums[1][tid][4] + s_sums[2][tid][4];

        const float inv = 1.0f / (WS * WS);
        const float C1 = 6.5025f;
        const float C2 = 58.5225f;
        float mx = S0 * inv, my = S1 * inv;
        float vx = S2 * inv - mx * mx;
        float vy = S3 * inv - my * my;
        float cv = S4 * inv - mx * my;
        float num = (2.0f * mx * my + C1) * (2.0f * cv + C2);
        float den = (mx * mx + my * my + C1) * (vx + vy + C2);
        float v = num / den;

#pragma unroll
        for (int off = 16; off; off >>= 1)
            v += __shfl_xor_sync(0xffffffffu, v, off);
        if (tid == 0) {
            g_partial[blockIdx.x] = v;
            __threadfence();
            unsigned int tk = atomicAdd(&g_ticket[b], 1u);
            s_ticket = tk;
        }
    }
    __syncthreads();

    // Last CTA of this batch folds the 32 row-partials.
    if (s_ticket == NWIN_Y - 1) {
        if (tid < 32) {
            volatile float* vp = (volatile float*)&g_partial[b * NWIN_Y];
            float v = vp[tid];
#pragma unroll
            for (int off = 16; off; off >>= 1)
                v += __shfl_xor_sync(0xffffffffu, v, off);
            if (tid == 0) {
                out[b] = (1.0f - v * (1.0f / (NWIN_X * NWIN_Y))) * 0.5f;
                g_ticket[b] = 0u;   // reset for next (graph-replayed) launch
            }
        }
    }
}

extern "C" void kernel_launch(void* const* d_in, const int* in_sizes, int n_in,
                              void* d_out, int out_size) {
    const float* x = (const float*)d_in[0];
    const float* y = (const float*)d_in[1];
    float* out = (float*)d_out;
    (void)in_sizes; (void)n_in; (void)out_size;

    ssim_fused_kernel<<<NBATCH * NWIN_Y, 384>>>(x, y, out);
}

// round 5
// speedup vs baseline: 1.0589x; 1.0589x over previous
#include <cuda_runtime.h>

// SSIM-style loss (sum over channels+window, /ws^2), single fused kernel.
// x, y: (32, 3, 512, 512) fp32. out: (32,) fp32.
//
// Grid 1024 = (batch, window-row); 256 threads/CTA = (row-half, float4-col).
// Each thread streams 8 rows x 3 channels (24 LDG.128 per input), coalesced.
// launch_bounds(256,7): regs<=36 -> 7 CTA/SM x 8 warps = 56 warps/SM, ONE wave.
// Half-partials combine in smem before SSIM nonlinearity.
// Per-batch ticket: last CTA of each batch folds 32 row-partials -> out[b].

#define IMG_H 512
#define IMG_W 512
#define NCH 3
#define WS 16
#define NWIN_X 32
#define NWIN_Y 32
#define NBATCH 32
#define W4 (IMG_W / 4)

static __device__ float        g_partial[NBATCH * NWIN_Y];
static __device__ unsigned int g_ticket[NBATCH];

__global__ __launch_bounds__(256, 7)
void ssim_fused_kernel(const float* __restrict__ x, const float* __restrict__ y,
                       float* __restrict__ out) {
    const int tid = threadIdx.x;
    const int hh  = tid >> 7;              // row half: 0 -> rows 0..7, 1 -> rows 8..15
    const int t   = tid & 127;             // float4 column 0..127
    const int br  = blockIdx.x & 31;       // window row
    const int b   = blockIdx.x >> 5;       // batch

    const size_t img = (size_t)NCH * IMG_H * IMG_W;
    const float4* __restrict__ xp = (const float4*)(x + (size_t)b * img);
    const float4* __restrict__ yp = (const float4*)(y + (size_t)b * img);

    float sx = 0.f, sy = 0.f, sxx = 0.f, syy = 0.f, sxy = 0.f;

#pragma unroll
    for (int c = 0; c < NCH; ++c) {
        size_t base = (size_t)c * (IMG_H * W4)
                    + (size_t)(br * WS + hh * 8) * W4 + t;
#pragma unroll
        for (int h0 = 0; h0 < 8; h0 += 2) {
            float4 vx0 = __ldcs(xp + base + (size_t)(h0    ) * W4);
            float4 vx1 = __ldcs(xp + base + (size_t)(h0 + 1) * W4);
            float4 vy0 = __ldcs(yp + base + (size_t)(h0    ) * W4);
            float4 vy1 = __ldcs(yp + base + (size_t)(h0 + 1) * W4);

            sx += (vx0.x + vx0.y) + (vx0.z + vx0.w);
            sy += (vy0.x + vy0.y) + (vy0.z + vy0.w);
            sxx = fmaf(vx0.x, vx0.x, sxx); sxx = fmaf(vx0.y, vx0.y, sxx);
            sxx = fmaf(vx0.z, vx0.z, sxx); sxx = fmaf(vx0.w, vx0.w, sxx);
            syy = fmaf(vy0.x, vy0.x, syy); syy = fmaf(vy0.y, vy0.y, syy);
            syy = fmaf(vy0.z, vy0.z, syy); syy = fmaf(vy0.w, vy0.w, syy);
            sxy = fmaf(vx0.x, vy0.x, sxy); sxy = fmaf(vx0.y, vy0.y, sxy);
            sxy = fmaf(vx0.z, vy0.z, sxy); sxy = fmaf(vx0.w, vy0.w, sxy);

            sx += (vx1.x + vx1.y) + (vx1.z + vx1.w);
            sy += (vy1.x + vy1.y) + (vy1.z + vy1.w);
            sxx = fmaf(vx1.x, vx1.x, sxx); sxx = fmaf(vx1.y, vx1.y, sxx);
            sxx = fmaf(vx1.z, vx1.z, sxx); sxx = fmaf(vx1.w, vx1.w, sxx);
            syy = fmaf(vy1.x, vy1.x, syy); syy = fmaf(vy1.y, vy1.y, syy);
            syy = fmaf(vy1.z, vy1.z, syy); syy = fmaf(vy1.w, vy1.w, syy);
            sxy = fmaf(vx1.x, vy1.x, sxy); sxy = fmaf(vx1.y, vy1.y, sxy);
            sxy = fmaf(vx1.z, vy1.z, sxy); sxy = fmaf(vx1.w, vy1.w, sxy);
        }
    }

    // fold 4 adjacent threads (16 cols of one window, this row-half, all chans)
#pragma unroll
    for (int off = 1; off < 4; off <<= 1) {
        sx  += __shfl_xor_sync(0xffffffffu, sx,  off);
        sy  += __shfl_xor_sync(0xffffffffu, sy,  off);
        sxx += __shfl_xor_sync(0xffffffffu, sxx, off);
        syy += __shfl_xor_sync(0xffffffffu, syy, off);
        sxy += __shfl_xor_sync(0xffffffffu, sxy, off);
    }

    __shared__ float s_sums[2][NWIN_X][5];
    __shared__ unsigned int s_ticket;
    if ((t & 3) == 0) {
        const int win = t >> 2;
        s_sums[hh][win][0] = sx;
        s_sums[hh][win][1] = sy;
        s_sums[hh][win][2] = sxx;
        s_sums[hh][win][3] = syy;
        s_sums[hh][win][4] = sxy;
    }
    __syncthreads();

    if (tid < 32) {
        float S0 = s_sums[0][tid][0] + s_sums[1][tid][0];
        float S1 = s_sums[0][tid][1] + s_sums[1][tid][1];
        float S2 = s_sums[0][tid][2] + s_sums[1][tid][2];
        float S3 = s_sums[0][tid][3] + s_sums[1][tid][3];
        float S4 = s_sums[0][tid][4] + s_sums[1][tid][4];

        const float inv = 1.0f / (WS * WS);
        const float C1 = 6.5025f;
        const float C2 = 58.5225f;
        float mx = S0 * inv, my = S1 * inv;
        float vx = S2 * inv - mx * mx;
        float vy = S3 * inv - my * my;
        float cv = S4 * inv - mx * my;
        float num = (2.0f * mx * my + C1) * (2.0f * cv + C2);
        float den = (mx * mx + my * my + C1) * (vx + vy + C2);
        float v = num / den;

#pragma unroll
        for (int off = 16; off; off >>= 1)
            v += __shfl_xor_sync(0xffffffffu, v, off);
        if (tid == 0) {
            g_partial[blockIdx.x] = v;
            __threadfence();
            unsigned int tk = atomicAdd(&g_ticket[b], 1u);
            s_ticket = tk;
        }
    }
    __syncthreads();

    // Last CTA of this batch folds the 32 row-partials.
    if (s_ticket == NWIN_Y - 1) {
        if (tid < 32) {
            volatile float* vp = (volatile float*)&g_partial[b * NWIN_Y];
            float v = vp[tid];
#pragma unroll
            for (int off = 16; off; off >>= 1)
                v += __shfl_xor_sync(0xffffffffu, v, off);
            if (tid == 0) {
                out[b] = (1.0f - v * (1.0f / (NWIN_X * NWIN_Y))) * 0.5f;
                g_ticket[b] = 0u;   // reset for next (graph-replayed) launch
            }
        }
    }
}

extern "C" void kernel_launch(void* const* d_in, const int* in_sizes, int n_in,
                              void* d_out, int out_size) {
    const float* x = (const float*)d_in[0];
    const float* y = (const float*)d_in[1];
    float* out = (float*)d_out;
    (void)in_sizes; (void)n_in; (void)out_size;

    ssim_fused_kernel<<<NBATCH * NWIN_Y, 256>>>(x, y, out);
}